// round 6
// baseline (speedup 1.0000x reference)
#include <cuda_runtime.h>
#include <cstdint>

// ---------------- problem constants ----------------
#define TB    32      // batch rows per CTA
#define NT    256     // threads per CTA (8 warps)
#define NCTA  2       // CTAs per SM
#define CH    16      // K-chunk rows staged in smem
#define DD    128     // module dim
#define APAD  132     // padded row stride for D=128 activation arrays
#define OPAD  260     // padded row stride for o (256) tile

// smem layout (floats)
#define XS        (TB*APAD)            // 4224
#define OFF_X     0                    // xbuf[4][TB][APAD] (aliases o-tile)
#define OFF_F0    (4*XS)
#define OFF_G     (5*XS)
#define OFF_W     (6*XS)               // [CH*DD] = 2048 (also Wz/Wg/Wg_last/Wa2 staging)
#define OFF_Z     (OFF_W + CH*DD)      // [TB][12]
#define OFF_LOG   (OFF_Z + TB*12)      // [TB][16]
#define OFF_P     (OFF_LOG + TB*16)    // [TB][16]
#define OFF_PL    (OFF_P + TB*16)      // [TB][4]
#define SMEM_FLOATS (OFF_PL + TB*4)    // 28928
#define SMEM_BYTES  (SMEM_FLOATS*4)    // 115712  (x2 CTAs = 231424 per SM)

// ---------------- packed f32x2 helpers ----------------
__device__ __forceinline__ uint64_t pack2(float lo, float hi) {
    uint64_t r;
    asm("mov.b64 %0, {%1, %2};" : "=l"(r) : "f"(lo), "f"(hi));
    return r;
}
__device__ __forceinline__ void unpack2(uint64_t v, float& lo, float& hi) {
    asm("mov.b64 {%0, %1}, %2;" : "=f"(lo), "=f"(hi) : "l"(v));
}
__device__ __forceinline__ void ffma2(uint64_t& d, uint64_t a, uint64_t b) {
    asm("fma.rn.f32x2 %0, %1, %2, %3;" : "=l"(d) : "l"(a), "l"(b), "l"(d));
}

// ---------------- GEMM: C(32 x K @ K x 128) + bias + relu ----------------
// Broadcast-W mapping:
//   warp w (0..7) owns cols [16w, 16w+16)  -> W reads warp-broadcast (N=1)
//   lane l owns row l                      -> A reads conflict-free (stride 132 fl)
// In-place safe (sOut may == sA): all A reads precede the final chunk sync.
__device__ __noinline__ void gemm_tile(
    const float* __restrict__ gW,     // K x 128 row-major, global
    const float* __restrict__ gBias,  // 128
    float* __restrict__ sA, int lda,
    float* __restrict__ sOut, int ldo,
    float* __restrict__ sW,           // CH*128 staging buffer
    int K)
{
    const int tid  = threadIdx.x;
    const int lane = tid & 31;
    const int c0   = (tid >> 5) * 16;   // warp's column base
    const int nch  = K / CH;

    // prefetch chunk 0 into registers (CH*DD = 2048 floats = 512 float4)
    float4 reg[2];
    {
        const float4* g4 = (const float4*)gW;
        #pragma unroll
        for (int i = 0; i < 2; ++i) reg[i] = g4[tid + i*NT];
    }

    // accumulators: 1 row x 16 cols, initialized from bias
    uint64_t acc[8];
    #pragma unroll
    for (int j = 0; j < 8; ++j)
        acc[j] = pack2(gBias[c0 + 2*j], gBias[c0 + 2*j + 1]);

    for (int ch = 0; ch < nch; ++ch) {
        {
            float4* sW4 = (float4*)sW;
            #pragma unroll
            for (int i = 0; i < 2; ++i) sW4[tid + i*NT] = reg[i];
        }
        __syncthreads();
        if (ch + 1 < nch) {
            const float4* g4 = (const float4*)(gW + (size_t)(ch + 1)*CH*DD);
            #pragma unroll
            for (int i = 0; i < 2; ++i) reg[i] = g4[tid + i*NT];
        }
        const float* ap = sA + lane*lda + ch*CH;
        #pragma unroll
        for (int kk = 0; kk < CH; kk += 4) {
            const float4 av = *(const float4*)(ap + kk);
            const float af[4] = {av.x, av.y, av.z, av.w};
            #pragma unroll
            for (int u = 0; u < 4; ++u) {
                const float* wrow = sW + (kk + u)*DD + c0;  // broadcast across lanes
                const ulonglong2 w0 = *(const ulonglong2*)(wrow);
                const ulonglong2 w1 = *(const ulonglong2*)(wrow + 4);
                const ulonglong2 w2 = *(const ulonglong2*)(wrow + 8);
                const ulonglong2 w3 = *(const ulonglong2*)(wrow + 12);
                const uint64_t p = pack2(af[u], af[u]);
                ffma2(acc[0], p, w0.x); ffma2(acc[1], p, w0.y);
                ffma2(acc[2], p, w1.x); ffma2(acc[3], p, w1.y);
                ffma2(acc[4], p, w2.x); ffma2(acc[5], p, w2.y);
                ffma2(acc[6], p, w3.x); ffma2(acc[7], p, w3.y);
            }
        }
        __syncthreads();
    }

    // epilogue: relu + store (after final sync -> in-place safe)
    {
        float* outp = sOut + lane*ldo + c0;
        #pragma unroll
        for (int q = 0; q < 2; ++q) {
            float f0, f1, f2, f3;
            unpack2(acc[4*q + 0], f0, f1); unpack2(acc[4*q + 1], f2, f3);
            float4 v0 = {fmaxf(f0,0.f), fmaxf(f1,0.f), fmaxf(f2,0.f), fmaxf(f3,0.f)};
            *(float4*)(outp + 8*q) = v0;
            unpack2(acc[4*q + 2], f0, f1); unpack2(acc[4*q + 3], f2, f3);
            float4 v1 = {fmaxf(f0,0.f), fmaxf(f1,0.f), fmaxf(f2,0.f), fmaxf(f3,0.f)};
            *(float4*)(outp + 8*q + 4) = v1;
        }
    }
    __syncthreads();
}

extern __shared__ float smem[];

__global__ __launch_bounds__(NT, NCTA)
void qnet_kernel(
    const float* __restrict__ o, const float* __restrict__ z_map, const float* __restrict__ cp,
    const float* __restrict__ Wb, const float* __restrict__ bb,
    const float* __restrict__ Wz, const float* __restrict__ bz,
    const float* __restrict__ Wm, const float* __restrict__ bm,
    const float* __restrict__ Wg, const float* __restrict__ Wg_last,
    const float* __restrict__ Wv, const float* __restrict__ bv,
    const float* __restrict__ Wa1, const float* __restrict__ ba1,
    const float* __restrict__ Wa2, const float* __restrict__ ba2,
    float* __restrict__ out)
{
    float* sX   = smem + OFF_X;     // xbuf[4]
    float* sF0  = smem + OFF_F0;
    float* sG   = smem + OFF_G;
    float* sW   = smem + OFF_W;
    float* sZ   = smem + OFF_Z;
    float* sLog = smem + OFF_LOG;
    float* sP   = smem + OFF_P;
    float* sPL  = smem + OFF_PL;
    float* sO   = sX;               // o-tile aliases xbuf[0..1]: 32*260=8320 < 2*XS

    const int tid  = threadIdx.x;
    const int row0 = blockIdx.x * TB;

    // ---- load o tile + z_in ----
    {
        const float4* g4 = (const float4*)(o + (size_t)row0 * 256);
        for (int i = tid; i < TB*64; i += NT) {
            int r = i >> 6, c = i & 63;
            *(float4*)(sO + r*OPAD + c*4) = g4[i];
        }
        for (int i = tid; i < TB*10; i += NT) {
            int r = i / 10, c = i - r*10;
            sZ[r*12 + c] = (c < 9) ? z_map[(size_t)(row0 + r)*9 + c] : cp[row0 + r];
        }
    }
    __syncthreads();

    // ---- f0 = relu(o @ Wb + bb) ----
    gemm_tile(Wb, bb, sO, OPAD, sF0, APAD, sW, 256);

    // ---- g = relu(z_in @ Wz + bz) * f0 ----
    for (int i = tid; i < 320; i += NT) ((float4*)sW)[i] = ((const float4*)Wz)[i];
    __syncthreads();
    for (int idx = tid; idx < TB*DD; idx += NT) {
        int b = idx >> 7, c = idx & 127;
        float a = bz[c];
        #pragma unroll
        for (int k = 0; k < 10; ++k) a = fmaf(sZ[b*12 + k], sW[k*DD + c], a);
        sG[b*APAD + c] = fmaxf(a, 0.f) * sF0[b*APAD + c];
    }
    __syncthreads();

    // ---- layer 0 ----
    for (int m = 0; m < 4; ++m)
        gemm_tile(Wm + (size_t)m*DD*DD, bm + m*DD, sF0, APAD, sX + m*XS, APAD, sW, DD);

    // ---- layers 1..3 ----
    for (int l = 1; l < 4; ++l) {
        {
            const float4* g4 = (const float4*)(Wg + (size_t)(l - 1)*DD*16);
            for (int i = tid; i < 512; i += NT) ((float4*)sW)[i] = g4[i];
        }
        __syncthreads();
        for (int idx = tid; idx < TB*16; idx += NT) {
            int b = idx >> 4, ij = idx & 15;
            const float* grow = sG + b*APAD;
            float a = 0.f;
            #pragma unroll 8
            for (int k = 0; k < DD; ++k) a = fmaf(grow[k], sW[k*16 + ij], a);
            sLog[idx] = a;
        }
        __syncthreads();
        // softmax over incoming i (axis 1)
        if (tid < TB*4) {
            int b = tid >> 2, j = tid & 3;
            float l0 = sLog[b*16 + j],     l1 = sLog[b*16 + 4 + j];
            float l2 = sLog[b*16 + 8 + j], l3 = sLog[b*16 + 12 + j];
            float mx = fmaxf(fmaxf(l0, l1), fmaxf(l2, l3));
            float e0 = expf(l0 - mx), e1 = expf(l1 - mx), e2 = expf(l2 - mx), e3 = expf(l3 - mx);
            float inv = 1.f / (e0 + e1 + e2 + e3);
            sP[b*16 + 0 + j]  = e0*inv;
            sP[b*16 + 4 + j]  = e1*inv;
            sP[b*16 + 8 + j]  = e2*inv;
            sP[b*16 + 12 + j] = e3*inv;
        }
        __syncthreads();
        // in-place mix: xin[j] = sum_i p[b,i,j] * x[i]
        for (int idx = tid; idx < TB*DD; idx += NT) {
            int b = idx >> 7, d = idx & 127;
            float x0 = sX[0*XS + b*APAD + d];
            float x1 = sX[1*XS + b*APAD + d];
            float x2 = sX[2*XS + b*APAD + d];
            float x3 = sX[3*XS + b*APAD + d];
            #pragma unroll
            for (int j = 0; j < 4; ++j) {
                float v = sP[b*16 + j]      * x0 + sP[b*16 + 4 + j]  * x1
                        + sP[b*16 + 8 + j]  * x2 + sP[b*16 + 12 + j] * x3;
                sX[j*XS + b*APAD + d] = v;
            }
        }
        __syncthreads();
        for (int m = 0; m < 4; ++m)
            gemm_tile(Wm + (size_t)(l*4 + m)*DD*DD, bm + (l*4 + m)*DD,
                      sX + m*XS, APAD, sX + m*XS, APAD, sW, DD);   // in-place
    }

    // ---- p_last (must precede sG overwrite) ----
    for (int i = tid; i < 128; i += NT) ((float4*)sW)[i] = ((const float4*)Wg_last)[i];
    __syncthreads();
    if (tid < TB*4) {
        int b = tid >> 2, m = tid & 3;
        const float* grow = sG + b*APAD;
        float a = 0.f;
        #pragma unroll 8
        for (int k = 0; k < DD; ++k) a = fmaf(grow[k], sW[k*4 + m], a);
        sLog[b*4 + m] = a;
    }
    __syncthreads();
    if (tid < TB) {
        int b = tid;
        float l0 = sLog[b*4], l1 = sLog[b*4+1], l2 = sLog[b*4+2], l3 = sLog[b*4+3];
        float mx = fmaxf(fmaxf(l0, l1), fmaxf(l2, l3));
        float e0 = expf(l0 - mx), e1 = expf(l1 - mx), e2 = expf(l2 - mx), e3 = expf(l3 - mx);
        float inv = 1.f / (e0 + e1 + e2 + e3);
        sPL[b*4] = e0*inv; sPL[b*4+1] = e1*inv; sPL[b*4+2] = e2*inv; sPL[b*4+3] = e3*inv;
    }
    __syncthreads();

    // ---- feature = sum_m p_last[m] * x[m] -> sF0 ----
    for (int idx = tid; idx < TB*DD; idx += NT) {
        int b = idx >> 7, d = idx & 127;
        float v = sPL[b*4 + 0] * sX[0*XS + b*APAD + d]
                + sPL[b*4 + 1] * sX[1*XS + b*APAD + d]
                + sPL[b*4 + 2] * sX[2*XS + b*APAD + d]
                + sPL[b*4 + 3] * sX[3*XS + b*APAD + d];
        sF0[b*APAD + d] = v;
    }
    __syncthreads();

    // ---- a1 = relu(feature @ Wa1 + ba1) -> sG (G dead now) ----
    gemm_tile(Wa1, ba1, sF0, APAD, sG, APAD, sW, DD);

    // ---- adv = a1 @ Wa2 + ba2 ----
    for (int i = tid; i < 256; i += NT) ((float4*)sW)[i] = ((const float4*)Wa2)[i];
    __syncthreads();
    for (int idx = tid; idx < TB*8; idx += NT) {
        int b = idx >> 3, a = idx & 7;
        const float* arow = sG + b*APAD;
        float acc = ba2[a];
        #pragma unroll 8
        for (int k = 0; k < DD; ++k) acc = fmaf(arow[k], sW[k*8 + a], acc);
        sLog[b*8 + a] = acc;
    }
    __syncthreads();

    // ---- value + dueling combine + store ----
    if (tid < TB) {
        int b = tid;
        float advv[8];
        float s = 0.f;
        #pragma unroll
        for (int a = 0; a < 8; ++a) { advv[a] = sLog[b*8 + a]; s += advv[a]; }
        float mean = s * 0.125f;
        const float* frow = sF0 + b*APAD;
        float v = bv[0];
        #pragma unroll 8
        for (int k = 0; k < DD; ++k) v = fmaf(frow[k], Wv[k], v);
        float* orow = out + (size_t)(row0 + b)*8;
        #pragma unroll
        for (int a = 0; a < 8; ++a) orow[a] = advv[a] - mean + v;
    }
}

extern "C" void kernel_launch(void* const* d_in, const int* in_sizes, int n_in,
                              void* d_out, int out_size) {
    const float* o       = (const float*)d_in[0];
    const float* z_map   = (const float*)d_in[1];
    const float* cp      = (const float*)d_in[2];
    const float* Wb      = (const float*)d_in[3];
    const float* bb      = (const float*)d_in[4];
    const float* Wz      = (const float*)d_in[5];
    const float* bz      = (const float*)d_in[6];
    const float* Wm      = (const float*)d_in[7];
    const float* bm      = (const float*)d_in[8];
    const float* Wg      = (const float*)d_in[9];
    const float* Wg_last = (const float*)d_in[10];
    const float* Wv      = (const float*)d_in[11];
    const float* bv      = (const float*)d_in[12];
    const float* Wa1     = (const float*)d_in[13];
    const float* ba1     = (const float*)d_in[14];
    const float* Wa2     = (const float*)d_in[15];
    const float* ba2     = (const float*)d_in[16];
    float* out = (float*)d_out;

    const int Btot = in_sizes[0] / 256;
    const int grid = (Btot + TB - 1) / TB;

    cudaFuncSetAttribute((const void*)qnet_kernel,
                         cudaFuncAttributeMaxDynamicSharedMemorySize, SMEM_BYTES);

    qnet_kernel<<<grid, NT, SMEM_BYTES>>>(
        o, z_map, cp, Wb, bb, Wz, bz, Wm, bm, Wg, Wg_last,
        Wv, bv, Wa1, ba1, Wa2, ba2, out);
}

// round 8
// speedup vs baseline: 1.3076x; 1.3076x over previous
#include <cuda_runtime.h>
#include <cstdint>

// ---------------- problem constants ----------------
#define TB    64      // batch rows per CTA
#define NT    512     // threads per CTA (16 warps)
#define CH    32      // K-chunk rows staged in smem
#define DD    128     // module dim
#define APAD  132     // padded row stride for D=128 activation arrays
#define OPAD  260     // padded row stride for o (256) tile

// smem layout (floats)
#define XS        (TB*APAD)            // 8448
#define OFF_X     0                    // xbuf[4][TB][APAD] (aliases o-tile)
#define OFF_F0    (4*XS)
#define OFF_G     (5*XS)
#define OFF_W     (6*XS)               // [CH*DD] = 4096 (also Wz/Wg/Wg_last/Wa2 staging)
#define OFF_Z     (OFF_W + CH*DD)      // [TB][12]
#define OFF_LOG   (OFF_Z + TB*12)      // [TB][16]
#define OFF_P     (OFF_LOG + TB*16)    // [TB][16]
#define OFF_PL    (OFF_P + TB*16)      // [TB][4]
#define SMEM_FLOATS (OFF_PL + TB*4)    // 57856
#define SMEM_BYTES  (SMEM_FLOATS*4)    // 231424

// ---------------- packed f32x2 helpers ----------------
__device__ __forceinline__ uint64_t pack2(float lo, float hi) {
    uint64_t r;
    asm("mov.b64 %0, {%1, %2};" : "=l"(r) : "f"(lo), "f"(hi));
    return r;
}
__device__ __forceinline__ void unpack2(uint64_t v, float& lo, float& hi) {
    asm("mov.b64 {%0, %1}, %2;" : "=f"(lo), "=f"(hi) : "l"(v));
}
__device__ __forceinline__ void ffma2(uint64_t& d, uint64_t a, uint64_t b) {
    asm("fma.rn.f32x2 %0, %1, %2, %3;" : "=l"(d) : "l"(a), "l"(b), "l"(d));
}

// ---------------- GEMM: C(64 x K @ K x 128) + bias + relu ----------------
// 16-warp balanced mapping (LDS wf == FMA cyc == 64 per k-step per SM):
//   warp w (0..15) owns cols [8w, 8w+8)  -> W reads warp-broadcast (2 wf/k)
//   lane l owns rows {l, l+32}           -> A reads conflict-free (2 wf/k)
// In-place safe (sOut may == sA): all A reads precede the final chunk sync.
__device__ __noinline__ void gemm_tile(
    const float* __restrict__ gW,     // K x 128 row-major, global
    const float* __restrict__ gBias,  // 128
    float* __restrict__ sA, int lda,
    float* __restrict__ sOut, int ldo,
    float* __restrict__ sW,           // CH*128 staging buffer
    int K)
{
    const int tid  = threadIdx.x;
    const int lane = tid & 31;
    const int c0   = (tid >> 5) * 8;    // warp's column base
    const int nch  = K / CH;

    // prefetch chunk 0 into registers (CH*DD = 4096 floats = 1024 float4)
    float4 reg[2];
    {
        const float4* g4 = (const float4*)gW;
        #pragma unroll
        for (int i = 0; i < 2; ++i) reg[i] = g4[tid + i*NT];
    }

    // accumulators: 2 rows x 8 cols, initialized from bias
    uint64_t acc[2][4];
    #pragma unroll
    for (int j = 0; j < 4; ++j) {
        acc[0][j] = pack2(gBias[c0 + 2*j], gBias[c0 + 2*j + 1]);
        acc[1][j] = acc[0][j];
    }

    for (int ch = 0; ch < nch; ++ch) {
        {
            float4* sW4 = (float4*)sW;
            #pragma unroll
            for (int i = 0; i < 2; ++i) sW4[tid + i*NT] = reg[i];
        }
        __syncthreads();
        if (ch + 1 < nch) {
            const float4* g4 = (const float4*)(gW + (size_t)(ch + 1)*CH*DD);
            #pragma unroll
            for (int i = 0; i < 2; ++i) reg[i] = g4[tid + i*NT];
        }
        const float* a0p = sA + lane*lda + ch*CH;
        const float* a1p = a0p + 32*lda;
        #pragma unroll
        for (int kk = 0; kk < CH; kk += 4) {
            const float4 av0 = *(const float4*)(a0p + kk);
            const float4 av1 = *(const float4*)(a1p + kk);
            const float a0f[4] = {av0.x, av0.y, av0.z, av0.w};
            const float a1f[4] = {av1.x, av1.y, av1.z, av1.w};
            #pragma unroll
            for (int u = 0; u < 4; ++u) {
                const float* wrow = sW + (kk + u)*DD + c0;  // broadcast across lanes
                const ulonglong2 w0 = *(const ulonglong2*)(wrow);
                const ulonglong2 w1 = *(const ulonglong2*)(wrow + 4);
                const uint64_t p0 = pack2(a0f[u], a0f[u]);
                const uint64_t p1 = pack2(a1f[u], a1f[u]);
                ffma2(acc[0][0], p0, w0.x); ffma2(acc[0][1], p0, w0.y);
                ffma2(acc[0][2], p0, w1.x); ffma2(acc[0][3], p0, w1.y);
                ffma2(acc[1][0], p1, w0.x); ffma2(acc[1][1], p1, w0.y);
                ffma2(acc[1][2], p1, w1.x); ffma2(acc[1][3], p1, w1.y);
            }
        }
        __syncthreads();
    }

    // epilogue: relu + store (after final sync -> in-place safe)
    #pragma unroll
    for (int r = 0; r < 2; ++r) {
        float* outp = sOut + (lane + r*32)*ldo + c0;
        float f0, f1, f2, f3;
        unpack2(acc[r][0], f0, f1); unpack2(acc[r][1], f2, f3);
        float4 v0 = {fmaxf(f0,0.f), fmaxf(f1,0.f), fmaxf(f2,0.f), fmaxf(f3,0.f)};
        *(float4*)(outp) = v0;
        unpack2(acc[r][2], f0, f1); unpack2(acc[r][3], f2, f3);
        float4 v1 = {fmaxf(f0,0.f), fmaxf(f1,0.f), fmaxf(f2,0.f), fmaxf(f3,0.f)};
        *(float4*)(outp + 4) = v1;
    }
    __syncthreads();
}

extern __shared__ float smem[];

__global__ __launch_bounds__(NT, 1)
void qnet_kernel(
    const float* __restrict__ o, const float* __restrict__ z_map, const float* __restrict__ cp,
    const float* __restrict__ Wb, const float* __restrict__ bb,
    const float* __restrict__ Wz, const float* __restrict__ bz,
    const float* __restrict__ Wm, const float* __restrict__ bm,
    const float* __restrict__ Wg, const float* __restrict__ Wg_last,
    const float* __restrict__ Wv, const float* __restrict__ bv,
    const float* __restrict__ Wa1, const float* __restrict__ ba1,
    const float* __restrict__ Wa2, const float* __restrict__ ba2,
    float* __restrict__ out)
{
    float* sX   = smem + OFF_X;     // xbuf[4]
    float* sF0  = smem + OFF_F0;
    float* sG   = smem + OFF_G;
    float* sW   = smem + OFF_W;
    float* sZ   = smem + OFF_Z;
    float* sLog = smem + OFF_LOG;
    float* sP   = smem + OFF_P;
    float* sPL  = smem + OFF_PL;
    float* sO   = sX;               // o-tile aliases xbuf[0..1]: 64*260=16640 < 2*XS

    const int tid  = threadIdx.x;
    const int row0 = blockIdx.x * TB;

    // ---- load o tile + z_in ----
    {
        const float4* g4 = (const float4*)(o + (size_t)row0 * 256);
        for (int i = tid; i < TB*64; i += NT) {
            int r = i >> 6, c = i & 63;
            *(float4*)(sO + r*OPAD + c*4) = g4[i];
        }
        for (int i = tid; i < TB*10; i += NT) {
            int r = i / 10, c = i - r*10;
            sZ[r*12 + c] = (c < 9) ? z_map[(size_t)(row0 + r)*9 + c] : cp[row0 + r];
        }
    }
    __syncthreads();

    // ---- f0 = relu(o @ Wb + bb) ----
    gemm_tile(Wb, bb, sO, OPAD, sF0, APAD, sW, 256);

    // ---- g = relu(z_in @ Wz + bz) * f0 ----
    for (int i = tid; i < 320; i += NT) ((float4*)sW)[i] = ((const float4*)Wz)[i];
    __syncthreads();
    for (int idx = tid; idx < TB*DD; idx += NT) {
        int b = idx >> 7, c = idx & 127;
        float a = bz[c];
        #pragma unroll
        for (int k = 0; k < 10; ++k) a = fmaf(sZ[b*12 + k], sW[k*DD + c], a);
        sG[b*APAD + c] = fmaxf(a, 0.f) * sF0[b*APAD + c];
    }
    __syncthreads();

    // ---- layer 0 ----
    for (int m = 0; m < 4; ++m)
        gemm_tile(Wm + (size_t)m*DD*DD, bm + m*DD, sF0, APAD, sX + m*XS, APAD, sW, DD);

    // ---- layers 1..3 ----
    for (int l = 1; l < 4; ++l) {
        {
            const float4* g4 = (const float4*)(Wg + (size_t)(l - 1)*DD*16);
            for (int i = tid; i < 512; i += NT) ((float4*)sW)[i] = g4[i];
        }
        __syncthreads();
        for (int idx = tid; idx < TB*16; idx += NT) {
            int b = idx >> 4, ij = idx & 15;
            const float* grow = sG + b*APAD;
            float a = 0.f;
            #pragma unroll 8
            for (int k = 0; k < DD; ++k) a = fmaf(grow[k], sW[k*16 + ij], a);
            sLog[idx] = a;
        }
        __syncthreads();
        // softmax over incoming i (axis 1)
        if (tid < TB*4) {
            int b = tid >> 2, j = tid & 3;
            float l0 = sLog[b*16 + j],     l1 = sLog[b*16 + 4 + j];
            float l2 = sLog[b*16 + 8 + j], l3 = sLog[b*16 + 12 + j];
            float mx = fmaxf(fmaxf(l0, l1), fmaxf(l2, l3));
            float e0 = expf(l0 - mx), e1 = expf(l1 - mx), e2 = expf(l2 - mx), e3 = expf(l3 - mx);
            float inv = 1.f / (e0 + e1 + e2 + e3);
            sP[b*16 + 0 + j]  = e0*inv;
            sP[b*16 + 4 + j]  = e1*inv;
            sP[b*16 + 8 + j]  = e2*inv;
            sP[b*16 + 12 + j] = e3*inv;
        }
        __syncthreads();
        // in-place mix: xin[j] = sum_i p[b,i,j] * x[i]
        for (int idx = tid; idx < TB*DD; idx += NT) {
            int b = idx >> 7, d = idx & 127;
            float x0 = sX[0*XS + b*APAD + d];
            float x1 = sX[1*XS + b*APAD + d];
            float x2 = sX[2*XS + b*APAD + d];
            float x3 = sX[3*XS + b*APAD + d];
            #pragma unroll
            for (int j = 0; j < 4; ++j) {
                float v = sP[b*16 + j]      * x0 + sP[b*16 + 4 + j]  * x1
                        + sP[b*16 + 8 + j]  * x2 + sP[b*16 + 12 + j] * x3;
                sX[j*XS + b*APAD + d] = v;
            }
        }
        __syncthreads();
        for (int m = 0; m < 4; ++m)
            gemm_tile(Wm + (size_t)(l*4 + m)*DD*DD, bm + (l*4 + m)*DD,
                      sX + m*XS, APAD, sX + m*XS, APAD, sW, DD);   // in-place
    }

    // ---- p_last (must precede sG overwrite) ----
    for (int i = tid; i < 128; i += NT) ((float4*)sW)[i] = ((const float4*)Wg_last)[i];
    __syncthreads();
    if (tid < TB*4) {
        int b = tid >> 2, m = tid & 3;
        const float* grow = sG + b*APAD;
        float a = 0.f;
        #pragma unroll 8
        for (int k = 0; k < DD; ++k) a = fmaf(grow[k], sW[k*4 + m], a);
        sLog[b*4 + m] = a;
    }
    __syncthreads();
    if (tid < TB) {
        int b = tid;
        float l0 = sLog[b*4], l1 = sLog[b*4+1], l2 = sLog[b*4+2], l3 = sLog[b*4+3];
        float mx = fmaxf(fmaxf(l0, l1), fmaxf(l2, l3));
        float e0 = expf(l0 - mx), e1 = expf(l1 - mx), e2 = expf(l2 - mx), e3 = expf(l3 - mx);
        float inv = 1.f / (e0 + e1 + e2 + e3);
        sPL[b*4] = e0*inv; sPL[b*4+1] = e1*inv; sPL[b*4+2] = e2*inv; sPL[b*4+3] = e3*inv;
    }
    __syncthreads();

    // ---- feature = sum_m p_last[m] * x[m] -> sF0 ----
    for (int idx = tid; idx < TB*DD; idx += NT) {
        int b = idx >> 7, d = idx & 127;
        float v = sPL[b*4 + 0] * sX[0*XS + b*APAD + d]
                + sPL[b*4 + 1] * sX[1*XS + b*APAD + d]
                + sPL[b*4 + 2] * sX[2*XS + b*APAD + d]
                + sPL[b*4 + 3] * sX[3*XS + b*APAD + d];
        sF0[b*APAD + d] = v;
    }
    __syncthreads();

    // ---- a1 = relu(feature @ Wa1 + ba1) -> sG (G dead now) ----
    gemm_tile(Wa1, ba1, sF0, APAD, sG, APAD, sW, DD);

    // ---- adv = a1 @ Wa2 + ba2 ----
    for (int i = tid; i < 256; i += NT) ((float4*)sW)[i] = ((const float4*)Wa2)[i];
    __syncthreads();
    for (int idx = tid; idx < TB*8; idx += NT) {
        int b = idx >> 3, a = idx & 7;
        const float* arow = sG + b*APAD;
        float acc = ba2[a];
        #pragma unroll 8
        for (int k = 0; k < DD; ++k) acc = fmaf(arow[k], sW[k*8 + a], acc);
        sLog[b*8 + a] = acc;
    }
    __syncthreads();

    // ---- value + dueling combine + store ----
    if (tid < TB) {
        int b = tid;
        float advv[8];
        float s = 0.f;
        #pragma unroll
        for (int a = 0; a < 8; ++a) { advv[a] = sLog[b*8 + a]; s += advv[a]; }
        float mean = s * 0.125f;
        const float* frow = sF0 + b*APAD;
        float v = bv[0];
        #pragma unroll 8
        for (int k = 0; k < DD; ++k) v = fmaf(frow[k], Wv[k], v);
        float* orow = out + (size_t)(row0 + b)*8;
        #pragma unroll
        for (int a = 0; a < 8; ++a) orow[a] = advv[a] - mean + v;
    }
}

extern "C" void kernel_launch(void* const* d_in, const int* in_sizes, int n_in,
                              void* d_out, int out_size) {
    const float* o       = (const float*)d_in[0];
    const float* z_map   = (const float*)d_in[1];
    const float* cp      = (const float*)d_in[2];
    const float* Wb      = (const float*)d_in[3];
    const float* bb      = (const float*)d_in[4];
    const float* Wz      = (const float*)d_in[5];
    const float* bz      = (const float*)d_in[6];
    const float* Wm      = (const float*)d_in[7];
    const float* bm      = (const float*)d_in[8];
    const float* Wg      = (const float*)d_in[9];
    const float* Wg_last = (const float*)d_in[10];
    const float* Wv      = (const float*)d_in[11];
    const float* bv      = (const float*)d_in[12];
    const float* Wa1     = (const float*)d_in[13];
    const float* ba1     = (const float*)d_in[14];
    const float* Wa2     = (const float*)d_in[15];
    const float* ba2     = (const float*)d_in[16];
    float* out = (float*)d_out;

    const int Btot = in_sizes[0] / 256;
    const int grid = (Btot + TB - 1) / TB;

    cudaFuncSetAttribute((const void*)qnet_kernel,
                         cudaFuncAttributeMaxDynamicSharedMemorySize, SMEM_BYTES);

    qnet_kernel<<<grid, NT, SMEM_BYTES>>>(
        o, z_map, cp, Wb, bb, Wz, bz, Wm, bm, Wg, Wg_last,
        Wv, bv, Wa1, ba1, Wa2, ba2, out);
}

// round 11
// speedup vs baseline: 1.3083x; 1.0005x over previous
#include <cuda_runtime.h>
#include <cstdint>

// ---------------- problem constants ----------------
#define TB    64      // batch rows per CTA
#define NT    512     // threads per CTA (16 warps)
#define CH    32      // K-chunk rows staged in smem
#define DD    128     // module dim
#define APAD  132     // padded row stride for D=128 activation arrays
#define OPAD  260     // padded row stride for o (256) tile

// smem layout (floats)
#define XS        (TB*APAD)            // 8448
#define OFF_X     0                    // xbuf[4][TB][APAD] (aliases o-tile)
#define OFF_F0    (4*XS)
#define OFF_G     (5*XS)
#define OFF_W     (6*XS)               // [CH*DD] = 4096 (also Wz/Wg/Wg_last/Wa2 staging)
#define OFF_Z     (OFF_W + CH*DD)      // [TB][12]
#define OFF_LOG   (OFF_Z + TB*12)      // [TB][16]
#define OFF_P     (OFF_LOG + TB*16)    // [TB][16]
#define OFF_PL    (OFF_P + TB*16)      // [TB][4]
#define SMEM_FLOATS (OFF_PL + TB*4)    // 57856
#define SMEM_BYTES  (SMEM_FLOATS*4)    // 231424

// ---------------- packed f32x2 helpers ----------------
__device__ __forceinline__ uint64_t pack2(float lo, float hi) {
    uint64_t r;
    asm("mov.b64 %0, {%1, %2};" : "=l"(r) : "f"(lo), "f"(hi));
    return r;
}
__device__ __forceinline__ void unpack2(uint64_t v, float& lo, float& hi) {
    asm("mov.b64 {%0, %1}, %2;" : "=f"(lo), "=f"(hi) : "l"(v));
}
__device__ __forceinline__ void ffma2(uint64_t& d, uint64_t a, uint64_t b) {
    asm("fma.rn.f32x2 %0, %1, %2, %3;" : "=l"(d) : "l"(a), "l"(b), "l"(d));
}

// ---------------- GEMM: C(64 x K @ K x 128) + bias + relu ----------------
// 16-warp balanced mapping (LDS wf == FMA cyc == 64 per k-step per SM):
//   warp w (0..15) owns cols [8w, 8w+8)  -> W reads warp-broadcast (2 wf/k)
//   lane l owns rows {l, l+32}           -> A reads conflict-free (2 wf/k)
// In-place safe (sOut may == sA): all A reads precede the final chunk sync.
__device__ __noinline__ void gemm_tile(
    const float* __restrict__ gW,     // K x 128 row-major, global
    const float* __restrict__ gBias,  // 128
    float* __restrict__ sA, int lda,
    float* __restrict__ sOut, int ldo,
    float* __restrict__ sW,           // CH*128 staging buffer
    int K)
{
    const int tid  = threadIdx.x;
    const int lane = tid & 31;
    const int c0   = (tid >> 5) * 8;    // warp's column base
    const int nch  = K / CH;

    // prefetch chunk 0 into registers (CH*DD = 4096 floats = 1024 float4)
    float4 reg[2];
    {
        const float4* g4 = (const float4*)gW;
        #pragma unroll
        for (int i = 0; i < 2; ++i) reg[i] = g4[tid + i*NT];
    }

    // accumulators: 2 rows x 8 cols, initialized from bias
    uint64_t acc[2][4];
    #pragma unroll
    for (int j = 0; j < 4; ++j) {
        acc[0][j] = pack2(gBias[c0 + 2*j], gBias[c0 + 2*j + 1]);
        acc[1][j] = acc[0][j];
    }

    for (int ch = 0; ch < nch; ++ch) {
        {
            float4* sW4 = (float4*)sW;
            #pragma unroll
            for (int i = 0; i < 2; ++i) sW4[tid + i*NT] = reg[i];
        }
        __syncthreads();
        if (ch + 1 < nch) {
            const float4* g4 = (const float4*)(gW + (size_t)(ch + 1)*CH*DD);
            #pragma unroll
            for (int i = 0; i < 2; ++i) reg[i] = g4[tid + i*NT];
        }
        const float* a0p = sA + lane*lda + ch*CH;
        const float* a1p = a0p + 32*lda;
        #pragma unroll
        for (int kk = 0; kk < CH; kk += 4) {
            const float4 av0 = *(const float4*)(a0p + kk);
            const float4 av1 = *(const float4*)(a1p + kk);
            const float a0f[4] = {av0.x, av0.y, av0.z, av0.w};
            const float a1f[4] = {av1.x, av1.y, av1.z, av1.w};
            #pragma unroll
            for (int u = 0; u < 4; ++u) {
                const float* wrow = sW + (kk + u)*DD + c0;  // broadcast across lanes
                const ulonglong2 w0 = *(const ulonglong2*)(wrow);
                const ulonglong2 w1 = *(const ulonglong2*)(wrow + 4);
                const uint64_t p0 = pack2(a0f[u], a0f[u]);
                const uint64_t p1 = pack2(a1f[u], a1f[u]);
                ffma2(acc[0][0], p0, w0.x); ffma2(acc[0][1], p0, w0.y);
                ffma2(acc[0][2], p0, w1.x); ffma2(acc[0][3], p0, w1.y);
                ffma2(acc[1][0], p1, w0.x); ffma2(acc[1][1], p1, w0.y);
                ffma2(acc[1][2], p1, w1.x); ffma2(acc[1][3], p1, w1.y);
            }
        }
        __syncthreads();
    }

    // epilogue: relu + store (after final sync -> in-place safe)
    #pragma unroll
    for (int r = 0; r < 2; ++r) {
        float* outp = sOut + (lane + r*32)*ldo + c0;
        float f0, f1, f2, f3;
        unpack2(acc[r][0], f0, f1); unpack2(acc[r][1], f2, f3);
        float4 v0 = {fmaxf(f0,0.f), fmaxf(f1,0.f), fmaxf(f2,0.f), fmaxf(f3,0.f)};
        *(float4*)(outp) = v0;
        unpack2(acc[r][2], f0, f1); unpack2(acc[r][3], f2, f3);
        float4 v1 = {fmaxf(f0,0.f), fmaxf(f1,0.f), fmaxf(f2,0.f), fmaxf(f3,0.f)};
        *(float4*)(outp + 4) = v1;
    }
    __syncthreads();
}

extern __shared__ float smem[];

__global__ __launch_bounds__(NT, 1)
void qnet_kernel(
    const float* __restrict__ o, const float* __restrict__ z_map, const float* __restrict__ cp,
    const float* __restrict__ Wb, const float* __restrict__ bb,
    const float* __restrict__ Wz, const float* __restrict__ bz,
    const float* __restrict__ Wm, const float* __restrict__ bm,
    const float* __restrict__ Wg, const float* __restrict__ Wg_last,
    const float* __restrict__ Wv, const float* __restrict__ bv,
    const float* __restrict__ Wa1, const float* __restrict__ ba1,
    const float* __restrict__ Wa2, const float* __restrict__ ba2,
    float* __restrict__ out)
{
    float* sX   = smem + OFF_X;     // xbuf[4]
    float* sF0  = smem + OFF_F0;
    float* sG   = smem + OFF_G;
    float* sW   = smem + OFF_W;
    float* sZ   = smem + OFF_Z;
    float* sLog = smem + OFF_LOG;
    float* sP   = smem + OFF_P;
    float* sPL  = smem + OFF_PL;
    float* sO   = sX;               // o-tile aliases xbuf[0..1]: 64*260=16640 < 2*XS

    const int tid  = threadIdx.x;
    const int row0 = blockIdx.x * TB;

    // ---- load o tile + z_in ----
    {
        const float4* g4 = (const float4*)(o + (size_t)row0 * 256);
        for (int i = tid; i < TB*64; i += NT) {
            int r = i >> 6, c = i & 63;
            *(float4*)(sO + r*OPAD + c*4) = g4[i];
        }
        for (int i = tid; i < TB*10; i += NT) {
            int r = i / 10, c = i - r*10;
            sZ[r*12 + c] = (c < 9) ? z_map[(size_t)(row0 + r)*9 + c] : cp[row0 + r];
        }
    }
    __syncthreads();

    // ---- f0 = relu(o @ Wb + bb) ----
    gemm_tile(Wb, bb, sO, OPAD, sF0, APAD, sW, 256);

    // ---- g = relu(z_in @ Wz + bz) * f0 ----
    for (int i = tid; i < 320; i += NT) ((float4*)sW)[i] = ((const float4*)Wz)[i];
    __syncthreads();
    for (int idx = tid; idx < TB*DD; idx += NT) {
        int b = idx >> 7, c = idx & 127;
        float a = bz[c];
        #pragma unroll
        for (int k = 0; k < 10; ++k) a = fmaf(sZ[b*12 + k], sW[k*DD + c], a);
        sG[b*APAD + c] = fmaxf(a, 0.f) * sF0[b*APAD + c];
    }
    __syncthreads();

    // ---- layer 0 ----
    for (int m = 0; m < 4; ++m)
        gemm_tile(Wm + (size_t)m*DD*DD, bm + m*DD, sF0, APAD, sX + m*XS, APAD, sW, DD);

    // ---- layers 1..3 ----
    for (int l = 1; l < 4; ++l) {
        {
            const float4* g4 = (const float4*)(Wg + (size_t)(l - 1)*DD*16);
            for (int i = tid; i < 512; i += NT) ((float4*)sW)[i] = g4[i];
        }
        __syncthreads();
        for (int idx = tid; idx < TB*16; idx += NT) {
            int b = idx >> 4, ij = idx & 15;
            const float* grow = sG + b*APAD;
            float a = 0.f;
            #pragma unroll 8
            for (int k = 0; k < DD; ++k) a = fmaf(grow[k], sW[k*16 + ij], a);
            sLog[idx] = a;
        }
        __syncthreads();
        // softmax over incoming i (axis 1)
        if (tid < TB*4) {
            int b = tid >> 2, j = tid & 3;
            float l0 = sLog[b*16 + j],     l1 = sLog[b*16 + 4 + j];
            float l2 = sLog[b*16 + 8 + j], l3 = sLog[b*16 + 12 + j];
            float mx = fmaxf(fmaxf(l0, l1), fmaxf(l2, l3));
            float e0 = expf(l0 - mx), e1 = expf(l1 - mx), e2 = expf(l2 - mx), e3 = expf(l3 - mx);
            float inv = 1.f / (e0 + e1 + e2 + e3);
            sP[b*16 + 0 + j]  = e0*inv;
            sP[b*16 + 4 + j]  = e1*inv;
            sP[b*16 + 8 + j]  = e2*inv;
            sP[b*16 + 12 + j] = e3*inv;
        }
        __syncthreads();
        // in-place mix: xin[j] = sum_i p[b,i,j] * x[i]
        for (int idx = tid; idx < TB*DD; idx += NT) {
            int b = idx >> 7, d = idx & 127;
            float x0 = sX[0*XS + b*APAD + d];
            float x1 = sX[1*XS + b*APAD + d];
            float x2 = sX[2*XS + b*APAD + d];
            float x3 = sX[3*XS + b*APAD + d];
            #pragma unroll
            for (int j = 0; j < 4; ++j) {
                float v = sP[b*16 + j]      * x0 + sP[b*16 + 4 + j]  * x1
                        + sP[b*16 + 8 + j]  * x2 + sP[b*16 + 12 + j] * x3;
                sX[j*XS + b*APAD + d] = v;
            }
        }
        __syncthreads();
        for (int m = 0; m < 4; ++m)
            gemm_tile(Wm + (size_t)(l*4 + m)*DD*DD, bm + (l*4 + m)*DD,
                      sX + m*XS, APAD, sX + m*XS, APAD, sW, DD);   // in-place
    }

    // ---- p_last (must precede sG overwrite) ----
    for (int i = tid; i < 128; i += NT) ((float4*)sW)[i] = ((const float4*)Wg_last)[i];
    __syncthreads();
    if (tid < TB*4) {
        int b = tid >> 2, m = tid & 3;
        const float* grow = sG + b*APAD;
        float a = 0.f;
        #pragma unroll 8
        for (int k = 0; k < DD; ++k) a = fmaf(grow[k], sW[k*4 + m], a);
        sLog[b*4 + m] = a;
    }
    __syncthreads();
    if (tid < TB) {
        int b = tid;
        float l0 = sLog[b*4], l1 = sLog[b*4+1], l2 = sLog[b*4+2], l3 = sLog[b*4+3];
        float mx = fmaxf(fmaxf(l0, l1), fmaxf(l2, l3));
        float e0 = expf(l0 - mx), e1 = expf(l1 - mx), e2 = expf(l2 - mx), e3 = expf(l3 - mx);
        float inv = 1.f / (e0 + e1 + e2 + e3);
        sPL[b*4] = e0*inv; sPL[b*4+1] = e1*inv; sPL[b*4+2] = e2*inv; sPL[b*4+3] = e3*inv;
    }
    __syncthreads();

    // ---- feature = sum_m p_last[m] * x[m] -> sF0 ----
    for (int idx = tid; idx < TB*DD; idx += NT) {
        int b = idx >> 7, d = idx & 127;
        float v = sPL[b*4 + 0] * sX[0*XS + b*APAD + d]
                + sPL[b*4 + 1] * sX[1*XS + b*APAD + d]
                + sPL[b*4 + 2] * sX[2*XS + b*APAD + d]
                + sPL[b*4 + 3] * sX[3*XS + b*APAD + d];
        sF0[b*APAD + d] = v;
    }
    __syncthreads();

    // ---- a1 = relu(feature @ Wa1 + ba1) -> sG (G dead now) ----
    gemm_tile(Wa1, ba1, sF0, APAD, sG, APAD, sW, DD);

    // ---- adv = a1 @ Wa2 + ba2 ----
    for (int i = tid; i < 256; i += NT) ((float4*)sW)[i] = ((const float4*)Wa2)[i];
    __syncthreads();
    for (int idx = tid; idx < TB*8; idx += NT) {
        int b = idx >> 3, a = idx & 7;
        const float* arow = sG + b*APAD;
        float acc = ba2[a];
        #pragma unroll 8
        for (int k = 0; k < DD; ++k) acc = fmaf(arow[k], sW[k*8 + a], acc);
        sLog[b*8 + a] = acc;
    }
    __syncthreads();

    // ---- value + dueling combine + store ----
    if (tid < TB) {
        int b = tid;
        float advv[8];
        float s = 0.f;
        #pragma unroll
        for (int a = 0; a < 8; ++a) { advv[a] = sLog[b*8 + a]; s += advv[a]; }
        float mean = s * 0.125f;
        const float* frow = sF0 + b*APAD;
        float v = bv[0];
        #pragma unroll 8
        for (int k = 0; k < DD; ++k) v = fmaf(frow[k], Wv[k], v);
        float* orow = out + (size_t)(row0 + b)*8;
        #pragma unroll
        for (int a = 0; a < 8; ++a) orow[a] = advv[a] - mean + v;
    }
}

extern "C" void kernel_launch(void* const* d_in, const int* in_sizes, int n_in,
                              void* d_out, int out_size) {
    const float* o       = (const float*)d_in[0];
    const float* z_map   = (const float*)d_in[1];
    const float* cp      = (const float*)d_in[2];
    const float* Wb      = (const float*)d_in[3];
    const float* bb      = (const float*)d_in[4];
    const float* Wz      = (const float*)d_in[5];
    const float* bz      = (const float*)d_in[6];
    const float* Wm      = (const float*)d_in[7];
    const float* bm      = (const float*)d_in[8];
    const float* Wg      = (const float*)d_in[9];
    const float* Wg_last = (const float*)d_in[10];
    const float* Wv      = (const float*)d_in[11];
    const float* bv      = (const float*)d_in[12];
    const float* Wa1     = (const float*)d_in[13];
    const float* ba1     = (const float*)d_in[14];
    const float* Wa2     = (const float*)d_in[15];
    const float* ba2     = (const float*)d_in[16];
    float* out = (float*)d_out;

    const int Btot = in_sizes[0] / 256;
    const int grid = (Btot + TB - 1) / TB;

    cudaFuncSetAttribute((const void*)qnet_kernel,
                         cudaFuncAttributeMaxDynamicSharedMemorySize, SMEM_BYTES);

    qnet_kernel<<<grid, NT, SMEM_BYTES>>>(
        o, z_map, cp, Wb, bb, Wz, bz, Wm, bm, Wg, Wg_last,
        Wv, bv, Wa1, ba1, Wa2, ba2, out);
}

// round 15
// speedup vs baseline: 2.3215x; 1.7745x over previous
#include <cuda_runtime.h>
#include <cstdint>

// ---------------- problem constants ----------------
#define TB    64      // batch rows per CTA
#define NT    256     // threads per CTA (8 warps)
#define CH    32      // K-chunk rows staged in smem
#define DD    128     // module dim
#define APAD  132     // padded row stride for activation arrays
#define OPAD  260     // padded row stride for o (256) tile
#define WPAD  136     // padded row stride for staged W chunk (conflict-free B frags)

// smem layout (floats)
#define XS        (TB*APAD)            // 8448
#define OFF_X     0                    // xbuf[4][TB][APAD] (aliases o-tile)
#define OFF_F0    (4*XS)
#define OFF_G     (5*XS)
#define OFF_W     (6*XS)               // CH*WPAD = 4352 (also small-matrix staging)
#define OFF_Z     (OFF_W + CH*WPAD)
#define OFF_LOG   (OFF_Z + TB*12)
#define OFF_P     (OFF_LOG + TB*16)
#define OFF_PL    (OFF_P + TB*16)
#define SMEM_FLOATS (OFF_PL + TB*4)    // 58112
#define SMEM_BYTES  (SMEM_FLOATS*4)    // 232448 (= sm_103 max dyn smem)

// preformatted (tf32-rounded) big weights, original layouts:
// Wb [256*128] @0, Wm [16*128*128] @32768, Wa1 [128*128] @294912
__device__ float g_wfmt[311296];

__device__ __forceinline__ float tf32r(float x) {
    float y; asm("cvt.rna.tf32.f32 %0, %1;" : "=f"(y) : "f"(x)); return y;
}

// D(16x8) += A(16x8 tf32) * B(8x8 tf32), fp32 accum
__device__ __forceinline__ void mma8(float* c, const float* a, float b0, float b1) {
    asm volatile(
        "mma.sync.aligned.m16n8k8.row.col.f32.tf32.tf32.f32 "
        "{%0,%1,%2,%3}, {%4,%5,%6,%7}, {%8,%9}, {%0,%1,%2,%3};"
        : "+f"(c[0]), "+f"(c[1]), "+f"(c[2]), "+f"(c[3])
        : "r"(__float_as_uint(a[0])), "r"(__float_as_uint(a[1])),
          "r"(__float_as_uint(a[2])), "r"(__float_as_uint(a[3])),
          "r"(__float_as_uint(b0)),  "r"(__float_as_uint(b1)));
}

// ---------- prep: tf32-round big weights ----------
__global__ void prep_kernel(const float* __restrict__ Wb,
                            const float* __restrict__ Wm,
                            const float* __restrict__ Wa1)
{
    int w = blockIdx.x * blockDim.x + threadIdx.x;
    if (w >= 311296) return;
    float v;
    if (w < 32768)       v = Wb[w];
    else if (w < 294912) v = Wm[w - 32768];
    else                 v = Wa1[w - 294912];
    g_wfmt[w] = tf32r(v);
}

// ---------------- GEMM: C(64 x K @ K x 128) + bias + relu via mma.sync tf32 ----------------
// warp w: rows [32*(w&1), +32), cols [32*(w>>1), +32)
// lane: gid = lane>>2 (0..7), tg = lane&3 (0..3)
__device__ __noinline__ void gemm_tile(
    const float* __restrict__ gW,     // K x 128 row-major (tf32-rounded), global
    const float* __restrict__ gBias,  // 128
    float* __restrict__ sA, int lda,  // activations (tf32-rounded), [64][lda]
    float* __restrict__ sOut, int ldo,
    float* __restrict__ sW,           // CH*WPAD staging
    int K, int rnd)
{
    const int tid  = threadIdx.x;
    const int lane = tid & 31;
    const int w    = tid >> 5;
    const int rowg = (w & 1) * 32;
    const int colg = (w >> 1) * 32;
    const int gid  = lane >> 2;
    const int tg   = lane & 3;
    const int nch  = K / CH;

    // prefetch chunk 0 (CH*128 = 4096 fl = 1024 float4)
    float4 reg[4];
    {
        const float4* g4 = (const float4*)gW;
        #pragma unroll
        for (int i = 0; i < 4; ++i) reg[i] = g4[tid + i*NT];
    }

    // accumulators: 2 rowtiles x 4 ntiles x 4
    float c[2][4][4];
    #pragma unroll
    for (int nt = 0; nt < 4; ++nt) {
        float b0 = gBias[colg + nt*8 + 2*tg];
        float b1 = gBias[colg + nt*8 + 2*tg + 1];
        #pragma unroll
        for (int rt = 0; rt < 2; ++rt) {
            c[rt][nt][0] = b0; c[rt][nt][1] = b1;
            c[rt][nt][2] = b0; c[rt][nt][3] = b1;
        }
    }

    for (int ch = 0; ch < nch; ++ch) {
        // commit prefetched chunk to padded staging
        {
            #pragma unroll
            for (int i = 0; i < 4; ++i) {
                int idx = tid + i*NT;
                int r = idx >> 5, c4 = idx & 31;
                *(float4*)(sW + r*WPAD + c4*4) = reg[i];
            }
        }
        __syncthreads();
        if (ch + 1 < nch) {
            const float4* g4 = (const float4*)(gW + (size_t)(ch + 1)*CH*DD);
            #pragma unroll
            for (int i = 0; i < 4; ++i) reg[i] = g4[tid + i*NT];
        }
        #pragma unroll
        for (int kk = 0; kk < 4; ++kk) {           // 4 x k8 subchunks
            const int k0 = kk * 8;
            // A fragments (2 row tiles)
            float a[2][4];
            #pragma unroll
            for (int rt = 0; rt < 2; ++rt) {
                const float* ap = sA + (rowg + rt*16 + gid)*lda + ch*CH + k0;
                a[rt][0] = ap[tg];
                a[rt][2] = ap[tg + 4];
                a[rt][1] = ap[8*lda + tg];
                a[rt][3] = ap[8*lda + tg + 4];
            }
            // B fragments + mma
            #pragma unroll
            for (int nt = 0; nt < 4; ++nt) {
                const float* bp = sW + (k0 + tg)*WPAD + colg + nt*8 + gid;
                float b0 = bp[0];
                float b1 = bp[4*WPAD];
                mma8(c[0][nt], a[0], b0, b1);
                mma8(c[1][nt], a[1], b0, b1);
            }
        }
        __syncthreads();
    }

    // epilogue: relu (+optional tf32 round) + store; in-place safe
    #pragma unroll
    for (int rt = 0; rt < 2; ++rt) {
        #pragma unroll
        for (int nt = 0; nt < 4; ++nt) {
            int R   = rowg + rt*16 + gid;
            int col = colg + nt*8 + 2*tg;
            float v0 = fmaxf(c[rt][nt][0], 0.f), v1 = fmaxf(c[rt][nt][1], 0.f);
            float v2 = fmaxf(c[rt][nt][2], 0.f), v3 = fmaxf(c[rt][nt][3], 0.f);
            if (rnd) { v0 = tf32r(v0); v1 = tf32r(v1); v2 = tf32r(v2); v3 = tf32r(v3); }
            *(float2*)(sOut + R*ldo + col)       = make_float2(v0, v1);
            *(float2*)(sOut + (R + 8)*ldo + col) = make_float2(v2, v3);
        }
    }
    __syncthreads();
}

extern __shared__ float smem[];

__global__ __launch_bounds__(NT, 1)
void qnet_kernel(
    const float* __restrict__ o, const float* __restrict__ z_map, const float* __restrict__ cp,
    const float* __restrict__ bb,
    const float* __restrict__ Wz, const float* __restrict__ bz,
    const float* __restrict__ bm,
    const float* __restrict__ Wg, const float* __restrict__ Wg_last,
    const float* __restrict__ Wv, const float* __restrict__ bv,
    const float* __restrict__ ba1,
    const float* __restrict__ Wa2, const float* __restrict__ ba2,
    float* __restrict__ out)
{
    float* sX   = smem + OFF_X;     // xbuf[4]
    float* sF0  = smem + OFF_F0;
    float* sG   = smem + OFF_G;
    float* sW   = smem + OFF_W;
    float* sZ   = smem + OFF_Z;
    float* sLog = smem + OFF_LOG;
    float* sP   = smem + OFF_P;
    float* sPL  = smem + OFF_PL;
    float* sO   = sX;               // o-tile aliases xbuf[0..1]

    const int tid  = threadIdx.x;
    const int row0 = blockIdx.x * TB;

    // ---- load o tile (tf32-rounded) + z_in ----
    {
        const float4* g4 = (const float4*)(o + (size_t)row0 * 256);
        for (int i = tid; i < TB*64; i += NT) {
            int r = i >> 6, c = i & 63;
            float4 v = g4[i];
            v.x = tf32r(v.x); v.y = tf32r(v.y); v.z = tf32r(v.z); v.w = tf32r(v.w);
            *(float4*)(sO + r*OPAD + c*4) = v;
        }
        for (int i = tid; i < TB*10; i += NT) {
            int r = i / 10, c = i - r*10;
            sZ[r*12 + c] = (c < 9) ? z_map[(size_t)(row0 + r)*9 + c] : cp[row0 + r];
        }
    }
    __syncthreads();

    // ---- f0 = relu(o @ Wb + bb), tf32-rounded output ----
    gemm_tile(g_wfmt, bb, sO, OPAD, sF0, APAD, sW, 256, 1);

    // ---- g = relu(z_in @ Wz + bz) * f0 (full fp32, small op) ----
    for (int i = tid; i < 320; i += NT) ((float4*)sW)[i] = ((const float4*)Wz)[i];
    __syncthreads();
    for (int idx = tid; idx < TB*DD; idx += NT) {
        int b = idx >> 7, c = idx & 127;
        float a = bz[c];
        #pragma unroll
        for (int k = 0; k < 10; ++k) a = fmaf(sZ[b*12 + k], sW[k*DD + c], a);
        sG[b*APAD + c] = fmaxf(a, 0.f) * sF0[b*APAD + c];
    }
    __syncthreads();

    // ---- layer 0 ----
    for (int m = 0; m < 4; ++m)
        gemm_tile(g_wfmt + 32768 + (size_t)m*DD*DD, bm + m*DD,
                  sF0, APAD, sX + m*XS, APAD, sW, DD, 1);

    // ---- layers 1..3 ----
    for (int l = 1; l < 4; ++l) {
        {
            const float4* g4 = (const float4*)(Wg + (size_t)(l - 1)*DD*16);
            for (int i = tid; i < 512; i += NT) ((float4*)sW)[i] = g4[i];
        }
        __syncthreads();
        for (int idx = tid; idx < TB*16; idx += NT) {
            int b = idx >> 4, ij = idx & 15;
            const float* grow = sG + b*APAD;
            float a = 0.f;
            #pragma unroll 8
            for (int k = 0; k < DD; ++k) a = fmaf(grow[k], sW[k*16 + ij], a);
            sLog[idx] = a;
        }
        __syncthreads();
        // softmax over incoming i (axis 1); NT == TB*4
        {
            int b = tid >> 2, j = tid & 3;
            float l0 = sLog[b*16 + j],     l1 = sLog[b*16 + 4 + j];
            float l2 = sLog[b*16 + 8 + j], l3 = sLog[b*16 + 12 + j];
            float mx = fmaxf(fmaxf(l0, l1), fmaxf(l2, l3));
            float e0 = expf(l0 - mx), e1 = expf(l1 - mx), e2 = expf(l2 - mx), e3 = expf(l3 - mx);
            float inv = 1.f / (e0 + e1 + e2 + e3);
            sP[b*16 + 0 + j]  = e0*inv;
            sP[b*16 + 4 + j]  = e1*inv;
            sP[b*16 + 8 + j]  = e2*inv;
            sP[b*16 + 12 + j] = e3*inv;
        }
        __syncthreads();
        // in-place mix (tf32-rounded, feeds next GEMM)
        for (int idx = tid; idx < TB*DD; idx += NT) {
            int b = idx >> 7, d = idx & 127;
            float x0 = sX[0*XS + b*APAD + d];
            float x1 = sX[1*XS + b*APAD + d];
            float x2 = sX[2*XS + b*APAD + d];
            float x3 = sX[3*XS + b*APAD + d];
            #pragma unroll
            for (int j = 0; j < 4; ++j) {
                float v = sP[b*16 + j]      * x0 + sP[b*16 + 4 + j]  * x1
                        + sP[b*16 + 8 + j]  * x2 + sP[b*16 + 12 + j] * x3;
                sX[j*XS + b*APAD + d] = tf32r(v);
            }
        }
        __syncthreads();
        for (int m = 0; m < 4; ++m)
            gemm_tile(g_wfmt + 32768 + (size_t)(l*4 + m)*DD*DD, bm + (l*4 + m)*DD,
                      sX + m*XS, APAD, sX + m*XS, APAD, sW, DD, 1);   // in-place
    }

    // ---- p_last (uses g) ----
    for (int i = tid; i < 128; i += NT) ((float4*)sW)[i] = ((const float4*)Wg_last)[i];
    __syncthreads();
    {
        int b = tid >> 2, m = tid & 3;
        const float* grow = sG + b*APAD;
        float a = 0.f;
        #pragma unroll 8
        for (int k = 0; k < DD; ++k) a = fmaf(grow[k], sW[k*4 + m], a);
        sLog[b*4 + m] = a;
    }
    __syncthreads();
    if (tid < TB) {
        int b = tid;
        float l0 = sLog[b*4], l1 = sLog[b*4+1], l2 = sLog[b*4+2], l3 = sLog[b*4+3];
        float mx = fmaxf(fmaxf(l0, l1), fmaxf(l2, l3));
        float e0 = expf(l0 - mx), e1 = expf(l1 - mx), e2 = expf(l2 - mx), e3 = expf(l3 - mx);
        float inv = 1.f / (e0 + e1 + e2 + e3);
        sPL[b*4] = e0*inv; sPL[b*4+1] = e1*inv; sPL[b*4+2] = e2*inv; sPL[b*4+3] = e3*inv;
    }
    __syncthreads();

    // ---- feature = sum_m p_last[m] * x[m] -> sF0 (rounded: feeds Wa1 GEMM) ----
    for (int idx = tid; idx < TB*DD; idx += NT) {
        int b = idx >> 7, d = idx & 127;
        float v = sPL[b*4 + 0] * sX[0*XS + b*APAD + d]
                + sPL[b*4 + 1] * sX[1*XS + b*APAD + d]
                + sPL[b*4 + 2] * sX[2*XS + b*APAD + d]
                + sPL[b*4 + 3] * sX[3*XS + b*APAD + d];
        sF0[b*APAD + d] = tf32r(v);
    }
    __syncthreads();

    // ---- a1 = relu(feature @ Wa1 + ba1) -> sG (full fp32 out; feeds fp32 Wa2) ----
    gemm_tile(g_wfmt + 294912, ba1, sF0, APAD, sG, APAD, sW, DD, 0);

    // ---- adv = a1 @ Wa2 + ba2 ----
    for (int i = tid; i < 256; i += NT) ((float4*)sW)[i] = ((const float4*)Wa2)[i];
    __syncthreads();
    for (int idx = tid; idx < TB*8; idx += NT) {
        int b = idx >> 3, a = idx & 7;
        const float* arow = sG + b*APAD;
        float acc = ba2[a];
        #pragma unroll 8
        for (int k = 0; k < DD; ++k) acc = fmaf(arow[k], sW[k*8 + a], acc);
        sLog[b*8 + a] = acc;
    }
    __syncthreads();

    // ---- value + dueling combine + store ----
    if (tid < TB) {
        int b = tid;
        float advv[8];
        float s = 0.f;
        #pragma unroll
        for (int a = 0; a < 8; ++a) { advv[a] = sLog[b*8 + a]; s += advv[a]; }
        float mean = s * 0.125f;
        const float* frow = sF0 + b*APAD;
        float v = bv[0];
        #pragma unroll 8
        for (int k = 0; k < DD; ++k) v = fmaf(frow[k], Wv[k], v);
        float* orow = out + (size_t)(row0 + b)*8;
        #pragma unroll
        for (int a = 0; a < 8; ++a) orow[a] = advv[a] - mean + v;
    }
}

extern "C" void kernel_launch(void* const* d_in, const int* in_sizes, int n_in,
                              void* d_out, int out_size) {
    const float* o       = (const float*)d_in[0];
    const float* z_map   = (const float*)d_in[1];
    const float* cp      = (const float*)d_in[2];
    const float* Wb      = (const float*)d_in[3];
    const float* bb      = (const float*)d_in[4];
    const float* Wz      = (const float*)d_in[5];
    const float* bz      = (const float*)d_in[6];
    const float* Wm      = (const float*)d_in[7];
    const float* bm      = (const float*)d_in[8];
    const float* Wg      = (const float*)d_in[9];
    const float* Wg_last = (const float*)d_in[10];
    const float* Wv      = (const float*)d_in[11];
    const float* bv      = (const float*)d_in[12];
    const float* Wa1     = (const float*)d_in[13];
    const float* ba1     = (const float*)d_in[14];
    const float* Wa2     = (const float*)d_in[15];
    const float* ba2     = (const float*)d_in[16];
    float* out = (float*)d_out;

    const int Btot = in_sizes[0] / 256;
    const int grid = (Btot + TB - 1) / TB;

    prep_kernel<<<(311296 + 255) / 256, 256>>>(Wb, Wm, Wa1);

    cudaFuncSetAttribute((const void*)qnet_kernel,
                         cudaFuncAttributeMaxDynamicSharedMemorySize, SMEM_BYTES);
    qnet_kernel<<<grid, NT, SMEM_BYTES>>>(
        o, z_map, cp, bb, Wz, bz, bm, Wg, Wg_last,
        Wv, bv, ba1, Wa2, ba2, out);
}

// round 17
// speedup vs baseline: 2.4768x; 1.0669x over previous
#include <cuda_runtime.h>
#include <cstdint>

// ---------------- problem constants ----------------
#define TB    64      // batch rows per CTA
#define NT    512     // threads per CTA (16 warps)
#define CH    32      // K-chunk rows staged in smem
#define DD    128     // module dim
#define APAD  132     // padded row stride for activation arrays
#define OPAD  260     // padded row stride for o (256) tile

// smem layout (floats)
#define XS        (TB*APAD)            // 8448
#define OFF_X     0                    // xbuf[4][TB][APAD] (aliases o-tile)
#define OFF_F0    (4*XS)
#define OFF_G     (5*XS)
#define OFF_W     (6*XS)               // 4352 fl area (frag chunk uses 4096; small staging too)
#define OFF_Z     (OFF_W + 4352)
#define OFF_LOG   (OFF_Z + TB*12)
#define OFF_P     (OFF_LOG + TB*16)
#define OFF_PL    (OFF_P + TB*16)
#define SMEM_FLOATS (OFF_PL + TB*4)    // 58112
#define SMEM_BYTES  (SMEM_FLOATS*4)    // 232448 (= sm_103 max dyn smem)

// preformatted weights in FRAG-READY layout, 76 chunks x 4096 floats:
// chunk = 32 k-rows of one GEMM; within chunk, float2[(s*128 + c)*4 + tg] =
//   { W[ch*32 + s*8 + tg][c], W[ch*32 + s*8 + tg + 4][c] }
// chunks 0..7: Wb (K=256); 8..71: Wm (16 gemms x 4); 72..75: Wa1
#define WCHUNK 4096
#define NWCH   76
__device__ float g_wfmt[NWCH * WCHUNK];

__device__ __forceinline__ float tf32r(float x) {
    float y; asm("cvt.rna.tf32.f32 %0, %1;" : "=f"(y) : "f"(x)); return y;
}

// D(16x8) += A(16x8 tf32) * B(8x8 tf32), fp32 accum
__device__ __forceinline__ void mma8(float* c, const float* a, float b0, float b1) {
    asm volatile(
        "mma.sync.aligned.m16n8k8.row.col.f32.tf32.tf32.f32 "
        "{%0,%1,%2,%3}, {%4,%5,%6,%7}, {%8,%9}, {%0,%1,%2,%3};"
        : "+f"(c[0]), "+f"(c[1]), "+f"(c[2]), "+f"(c[3])
        : "r"(__float_as_uint(a[0])), "r"(__float_as_uint(a[1])),
          "r"(__float_as_uint(a[2])), "r"(__float_as_uint(a[3])),
          "r"(__float_as_uint(b0)),  "r"(__float_as_uint(b1)));
}

// ---------- prep: tf32-round + repack big weights into frag-ready chunks ----------
__global__ void prep_kernel(const float* __restrict__ Wb,
                            const float* __restrict__ Wm,
                            const float* __restrict__ Wa1)
{
    int t = blockIdx.x * blockDim.x + threadIdx.x;   // one float2 per thread
    if (t >= NWCH * WCHUNK / 2) return;
    int ch = t >> 11;                 // chunk 0..75
    int r  = t & 2047;
    int s  = r >> 9;                  // k8 sub 0..3
    int c  = (r >> 2) & 127;          // col 0..127
    int tg = r & 3;
    int kl = s * 8 + tg;              // local k of lo element
    const float* src;
    int ck;                           // chunk-local base row in source
    if (ch < 8)       { src = Wb;  ck = ch * 32; }
    else if (ch < 72) { src = Wm + (size_t)((ch - 8) >> 2) * 16384; ck = ((ch - 8) & 3) * 32; }
    else              { src = Wa1; ck = (ch - 72) * 32; }
    float lo = tf32r(src[(ck + kl) * 128 + c]);
    float hi = tf32r(src[(ck + kl + 4) * 128 + c]);
    ((float2*)g_wfmt)[t] = make_float2(lo, hi);
}

// ---------------- GEMM: C(64 x K @ K x 128) + bias + relu via mma.sync tf32 ----------------
// 16 warps: warp w -> rows [16*(w&3), +16), cols [32*(w>>2), +32)
// lane: gid = lane>>2 (0..7), tg = lane&3 (0..3)
__device__ __noinline__ void gemm_tile(
    const float* __restrict__ gW,     // frag-ready chunks, global
    const float* __restrict__ gBias,  // 128
    float* __restrict__ sA, int lda,  // activations (tf32-rounded), [64][lda]
    float* __restrict__ sOut, int ldo,
    float* __restrict__ sW,           // 4096-fl staging
    int K, int rnd)
{
    const int tid  = threadIdx.x;
    const int lane = tid & 31;
    const int w    = tid >> 5;
    const int rowg = (w & 3) * 16;
    const int colg = (w >> 2) * 32;
    const int gid  = lane >> 2;
    const int tg   = lane & 3;
    const int nch  = K / CH;

    // prefetch chunk 0 (4096 fl = 1024 float4; 2 per thread)
    float4 reg[2];
    {
        const float4* g4 = (const float4*)gW;
        #pragma unroll
        for (int i = 0; i < 2; ++i) reg[i] = g4[tid + i*NT];
    }

    // accumulators: 4 ntiles x 4, init from bias
    float c[4][4];
    #pragma unroll
    for (int nt = 0; nt < 4; ++nt) {
        float b0 = gBias[colg + nt*8 + 2*tg];
        float b1 = gBias[colg + nt*8 + 2*tg + 1];
        c[nt][0] = b0; c[nt][1] = b1; c[nt][2] = b0; c[nt][3] = b1;
    }

    for (int ch = 0; ch < nch; ++ch) {
        {
            float4* s4 = (float4*)sW;
            #pragma unroll
            for (int i = 0; i < 2; ++i) s4[tid + i*NT] = reg[i];
        }
        __syncthreads();
        if (ch + 1 < nch) {
            const float4* g4 = (const float4*)(gW + (size_t)(ch + 1)*WCHUNK);
            #pragma unroll
            for (int i = 0; i < 2; ++i) reg[i] = g4[tid + i*NT];
        }
        const float2* sW2 = (const float2*)sW;
        #pragma unroll
        for (int s = 0; s < 4; ++s) {
            // A fragment: rows rowg+gid, rowg+gid+8; cols k0+tg, k0+tg+4
            const float* ap = sA + (rowg + gid)*lda + ch*CH + s*8;
            float a[4];
            a[0] = ap[tg];
            a[1] = ap[8*lda + tg];
            a[2] = ap[tg + 4];
            a[3] = ap[8*lda + tg + 4];
            // B fragments: one LDS.64 per ntile
            #pragma unroll
            for (int nt = 0; nt < 4; ++nt) {
                float2 b = sW2[(s*128 + colg + nt*8 + gid)*4 + tg];
                mma8(c[nt], a, b.x, b.y);
            }
        }
        __syncthreads();
    }

    // epilogue: relu (+optional tf32 round); in-place safe (after final sync)
    #pragma unroll
    for (int nt = 0; nt < 4; ++nt) {
        int R   = rowg + gid;
        int col = colg + nt*8 + 2*tg;
        float v0 = fmaxf(c[nt][0], 0.f), v1 = fmaxf(c[nt][1], 0.f);
        float v2 = fmaxf(c[nt][2], 0.f), v3 = fmaxf(c[nt][3], 0.f);
        if (rnd) { v0 = tf32r(v0); v1 = tf32r(v1); v2 = tf32r(v2); v3 = tf32r(v3); }
        *(float2*)(sOut + R*ldo + col)       = make_float2(v0, v1);
        *(float2*)(sOut + (R + 8)*ldo + col) = make_float2(v2, v3);
    }
    __syncthreads();
}

extern __shared__ float smem[];

__global__ __launch_bounds__(NT, 1)
void qnet_kernel(
    const float* __restrict__ o, const float* __restrict__ z_map, const float* __restrict__ cp,
    const float* __restrict__ bb,
    const float* __restrict__ Wz, const float* __restrict__ bz,
    const float* __restrict__ bm,
    const float* __restrict__ Wg, const float* __restrict__ Wg_last,
    const float* __restrict__ Wv, const float* __restrict__ bv,
    const float* __restrict__ ba1,
    const float* __restrict__ Wa2, const float* __restrict__ ba2,
    float* __restrict__ out)
{
    float* sX   = smem + OFF_X;     // xbuf[4]
    float* sF0  = smem + OFF_F0;
    float* sG   = smem + OFF_G;
    float* sW   = smem + OFF_W;
    float* sZ   = smem + OFF_Z;
    float* sLog = smem + OFF_LOG;
    float* sP   = smem + OFF_P;
    float* sPL  = smem + OFF_PL;
    float* sO   = sX;               // o-tile aliases xbuf[0..1]

    const int tid  = threadIdx.x;
    const int row0 = blockIdx.x * TB;

    // ---- load o tile (tf32-rounded) + z_in ----
    {
        const float4* g4 = (const float4*)(o + (size_t)row0 * 256);
        for (int i = tid; i < TB*64; i += NT) {
            int r = i >> 6, c = i & 63;
            float4 v = g4[i];
            v.x = tf32r(v.x); v.y = tf32r(v.y); v.z = tf32r(v.z); v.w = tf32r(v.w);
            *(float4*)(sO + r*OPAD + c*4) = v;
        }
        for (int i = tid; i < TB*10; i += NT) {
            int r = i / 10, c = i - r*10;
            sZ[r*12 + c] = (c < 9) ? z_map[(size_t)(row0 + r)*9 + c] : cp[row0 + r];
        }
    }
    __syncthreads();

    // ---- f0 = relu(o @ Wb + bb), tf32-rounded output ----
    gemm_tile(g_wfmt, bb, sO, OPAD, sF0, APAD, sW, 256, 1);

    // ---- g = relu(z_in @ Wz + bz) * f0 (full fp32, small op) ----
    for (int i = tid; i < 320; i += NT) ((float4*)sW)[i] = ((const float4*)Wz)[i];
    __syncthreads();
    for (int idx = tid; idx < TB*DD; idx += NT) {
        int b = idx >> 7, c = idx & 127;
        float a = bz[c];
        #pragma unroll
        for (int k = 0; k < 10; ++k) a = fmaf(sZ[b*12 + k], sW[k*DD + c], a);
        sG[b*APAD + c] = fmaxf(a, 0.f) * sF0[b*APAD + c];
    }
    __syncthreads();

    // ---- layer 0 ----
    for (int m = 0; m < 4; ++m)
        gemm_tile(g_wfmt + (size_t)(8 + m*4)*WCHUNK, bm + m*DD,
                  sF0, APAD, sX + m*XS, APAD, sW, DD, 1);

    // ---- layers 1..3 ----
    for (int l = 1; l < 4; ++l) {
        {
            const float4* g4 = (const float4*)(Wg + (size_t)(l - 1)*DD*16);
            for (int i = tid; i < 512; i += NT) ((float4*)sW)[i] = g4[i];
        }
        __syncthreads();
        for (int idx = tid; idx < TB*16; idx += NT) {
            int b = idx >> 4, ij = idx & 15;
            const float* grow = sG + b*APAD;
            float a = 0.f;
            #pragma unroll 8
            for (int k = 0; k < DD; ++k) a = fmaf(grow[k], sW[k*16 + ij], a);
            sLog[idx] = a;
        }
        __syncthreads();
        // softmax over incoming i (axis 1)
        if (tid < TB*4) {
            int b = tid >> 2, j = tid & 3;
            float l0 = sLog[b*16 + j],     l1 = sLog[b*16 + 4 + j];
            float l2 = sLog[b*16 + 8 + j], l3 = sLog[b*16 + 12 + j];
            float mx = fmaxf(fmaxf(l0, l1), fmaxf(l2, l3));
            float e0 = expf(l0 - mx), e1 = expf(l1 - mx), e2 = expf(l2 - mx), e3 = expf(l3 - mx);
            float inv = 1.f / (e0 + e1 + e2 + e3);
            sP[b*16 + 0 + j]  = e0*inv;
            sP[b*16 + 4 + j]  = e1*inv;
            sP[b*16 + 8 + j]  = e2*inv;
            sP[b*16 + 12 + j] = e3*inv;
        }
        __syncthreads();
        // in-place mix (tf32-rounded, feeds next GEMM)
        for (int idx = tid; idx < TB*DD; idx += NT) {
            int b = idx >> 7, d = idx & 127;
            float x0 = sX[0*XS + b*APAD + d];
            float x1 = sX[1*XS + b*APAD + d];
            float x2 = sX[2*XS + b*APAD + d];
            float x3 = sX[3*XS + b*APAD + d];
            #pragma unroll
            for (int j = 0; j < 4; ++j) {
                float v = sP[b*16 + j]      * x0 + sP[b*16 + 4 + j]  * x1
                        + sP[b*16 + 8 + j]  * x2 + sP[b*16 + 12 + j] * x3;
                sX[j*XS + b*APAD + d] = tf32r(v);
            }
        }
        __syncthreads();
        for (int m = 0; m < 4; ++m)
            gemm_tile(g_wfmt + (size_t)(8 + (l*4 + m)*4)*WCHUNK, bm + (l*4 + m)*DD,
                      sX + m*XS, APAD, sX + m*XS, APAD, sW, DD, 1);   // in-place
    }

    // ---- p_last (uses g) ----
    for (int i = tid; i < 128; i += NT) ((float4*)sW)[i] = ((const float4*)Wg_last)[i];
    __syncthreads();
    if (tid < TB*4) {
        int b = tid >> 2, m = tid & 3;
        const float* grow = sG + b*APAD;
        float a = 0.f;
        #pragma unroll 8
        for (int k = 0; k < DD; ++k) a = fmaf(grow[k], sW[k*4 + m], a);
        sLog[b*4 + m] = a;
    }
    __syncthreads();
    if (tid < TB) {
        int b = tid;
        float l0 = sLog[b*4], l1 = sLog[b*4+1], l2 = sLog[b*4+2], l3 = sLog[b*4+3];
        float mx = fmaxf(fmaxf(l0, l1), fmaxf(l2, l3));
        float e0 = expf(l0 - mx), e1 = expf(l1 - mx), e2 = expf(l2 - mx), e3 = expf(l3 - mx);
        float inv = 1.f / (e0 + e1 + e2 + e3);
        sPL[b*4] = e0*inv; sPL[b*4+1] = e1*inv; sPL[b*4+2] = e2*inv; sPL[b*4+3] = e3*inv;
    }
    __syncthreads();

    // ---- feature = sum_m p_last[m] * x[m] -> sF0 (rounded: feeds Wa1 GEMM) ----
    for (int idx = tid; idx < TB*DD; idx += NT) {
        int b = idx >> 7, d = idx & 127;
        float v = sPL[b*4 + 0] * sX[0*XS + b*APAD + d]
                + sPL[b*4 + 1] * sX[1*XS + b*APAD + d]
                + sPL[b*4 + 2] * sX[2*XS + b*APAD + d]
                + sPL[b*4 + 3] * sX[3*XS + b*APAD + d];
        sF0[b*APAD + d] = tf32r(v);
    }
    __syncthreads();

    // ---- a1 = relu(feature @ Wa1 + ba1) -> sG (full fp32 out; feeds fp32 Wa2) ----
    gemm_tile(g_wfmt + (size_t)72*WCHUNK, ba1, sF0, APAD, sG, APAD, sW, DD, 0);

    // ---- adv = a1 @ Wa2 + ba2 ----
    for (int i = tid; i < 256; i += NT) ((float4*)sW)[i] = ((const float4*)Wa2)[i];
    __syncthreads();
    {
        int b = tid >> 3, a = tid & 7;   // NT == TB*8
        const float* arow = sG + b*APAD;
        float acc = ba2[a];
        #pragma unroll 8
        for (int k = 0; k < DD; ++k) acc = fmaf(arow[k], sW[k*8 + a], acc);
        sLog[b*8 + a] = acc;
    }
    __syncthreads();

    // ---- value + dueling combine + store ----
    if (tid < TB) {
        int b = tid;
        float advv[8];
        float s = 0.f;
        #pragma unroll
        for (int a = 0; a < 8; ++a) { advv[a] = sLog[b*8 + a]; s += advv[a]; }
        float mean = s * 0.125f;
        const float* frow = sF0 + b*APAD;
        float v = bv[0];
        #pragma unroll 8
        for (int k = 0; k < DD; ++k) v = fmaf(frow[k], Wv[k], v);
        float* orow = out + (size_t)(row0 + b)*8;
        #pragma unroll
        for (int a = 0; a < 8; ++a) orow[a] = advv[a] - mean + v;
    }
}

extern "C" void kernel_launch(void* const* d_in, const int* in_sizes, int n_in,
                              void* d_out, int out_size) {
    const float* o       = (const float*)d_in[0];
    const float* z_map   = (const float*)d_in[1];
    const float* cp      = (const float*)d_in[2];
    const float* Wb      = (const float*)d_in[3];
    const float* bb      = (const float*)d_in[4];
    const float* Wz      = (const float*)d_in[5];
    const float* bz      = (const float*)d_in[6];
    const float* Wm      = (const float*)d_in[7];
    const float* bm      = (const float*)d_in[8];
    const float* Wg      = (const float*)d_in[9];
    const float* Wg_last = (const float*)d_in[10];
    const float* Wv      = (const float*)d_in[11];
    const float* bv      = (const float*)d_in[12];
    const float* Wa1     = (const float*)d_in[13];
    const float* ba1     = (const float*)d_in[14];
    const float* Wa2     = (const float*)d_in[15];
    const float* ba2     = (const float*)d_in[16];
    float* out = (float*)d_out;

    const int Btot = in_sizes[0] / 256;
    const int grid = (Btot + TB - 1) / TB;

    prep_kernel<<<(NWCH * WCHUNK / 2 + 255) / 256, 256>>>(Wb, Wm, Wa1);

    cudaFuncSetAttribute((const void*)qnet_kernel,
                         cudaFuncAttributeMaxDynamicSharedMemorySize, SMEM_BYTES);
    qnet_kernel<<<grid, NT, SMEM_BYTES>>>(
        o, z_map, cp, bb, Wz, bz, bm, Wg, Wg_last,
        Wv, bv, ba1, Wa2, ba2, out);
}